// round 10
// baseline (speedup 1.0000x reference)
#include <cuda_runtime.h>
#include <cuda_fp16.h>
#include <stdint.h>
#include <math.h>

#define B_ 4
#define L_ 1024
#define H_ 8
#define D_ 64
#define BH_ 32
#define INV_TEMP 0.125f

typedef unsigned int u32;

__device__ __align__(16) __half g_qh[BH_ * L_ * D_];
__device__ __align__(16) __half g_kh[BH_ * L_ * D_];
__device__ __align__(16) __half g_vt[BH_ * D_ * L_];   // V transposed: [bh][d][l]

__device__ __forceinline__ void hmma(float* c, const u32* a, u32 b0, u32 b1) {
    asm volatile(
        "mma.sync.aligned.m16n8k16.row.col.f32.f16.f16.f32 "
        "{%0,%1,%2,%3}, {%4,%5,%6,%7}, {%8,%9}, {%0,%1,%2,%3};"
        : "+f"(c[0]), "+f"(c[1]), "+f"(c[2]), "+f"(c[3])
        : "r"(a[0]), "r"(a[1]), "r"(a[2]), "r"(a[3]), "r"(b0), "r"(b1));
}
__device__ __forceinline__ u32 pack_h2(float a, float b) {
    half2 h = __floats2half2_rn(a, b);
    return *(u32*)&h;
}

// ---- prep: L2-normalize q,k -> fp16 [bh][l][d]; 2 rows per warp ----
__global__ void prep_kernel(const float* __restrict__ q,
                            const float* __restrict__ k) {
    const int gw = (blockIdx.x * blockDim.x + threadIdx.x) >> 5;
    const int lane = threadIdx.x & 31;
    const int r = gw * 2 + (lane >> 4);
    const int c4 = lane & 15;
    const int b = r / (L_ * H_);
    const int rem = r % (L_ * H_);
    const int l = rem / H_;
    const int h = rem % H_;
    const long src = (((long)b * L_ + l) * H_ + h) * D_ + c4 * 4;
    const long dst = (((long)b * H_ + h) * L_ + l) * D_ + c4 * 4;

    float4 qv = *(const float4*)(q + src);
    float ss = qv.x * qv.x + qv.y * qv.y + qv.z * qv.z + qv.w * qv.w;
#pragma unroll
    for (int o = 1; o < 16; o <<= 1) ss += __shfl_xor_sync(0xffffffffu, ss, o);
    float sc = 1.0f / fmaxf(sqrtf(ss), 1e-8f);
    uint2 pk;
    pk.x = pack_h2(qv.x * sc, qv.y * sc);
    pk.y = pack_h2(qv.z * sc, qv.w * sc);
    *(uint2*)(g_qh + dst) = pk;

    float4 kv = *(const float4*)(k + src);
    ss = kv.x * kv.x + kv.y * kv.y + kv.z * kv.z + kv.w * kv.w;
#pragma unroll
    for (int o = 1; o < 16; o <<= 1) ss += __shfl_xor_sync(0xffffffffu, ss, o);
    sc = 1.0f / fmaxf(sqrtf(ss), 1e-8f);
    pk.x = pack_h2(kv.x * sc, kv.y * sc);
    pk.y = pack_h2(kv.z * sc, kv.w * sc);
    *(uint2*)(g_kh + dst) = pk;
}

// ---- vt: transpose V [B,L,H,D] f32 -> g_vt [bh][d][l] f16, via smem tile ----
#define VT_S 73
__global__ void vt_kernel(const float* __restrict__ v) {
    __shared__ __half tile[128 * VT_S];
    const int t = threadIdx.x;
    const int lc = blockIdx.x;            // l-chunk of 128
    const int bh = blockIdx.y;
    const int b = bh >> 3;
    const int h = bh & 7;

#pragma unroll
    for (int i = 0; i < 32; i++) {
        const int idx = t + 256 * i;      // over 128*64
        const int row = idx >> 6;
        const int col = idx & 63;
        const long src = (((long)(b * 1024 + lc * 128 + row)) * 8 + h) * 64 + col;
        tile[row * VT_S + col] = __float2half(v[src]);
    }
    __syncthreads();

#pragma unroll
    for (int pass = 0; pass < 4; pass++) {
        const int d = (t >> 4) + 16 * pass;
        const int ls = t & 15;
        __half hbuf[8];
#pragma unroll
        for (int kk = 0; kk < 8; kk++) hbuf[kk] = tile[(ls * 8 + kk) * VT_S + d];
        uint4 w;
        half2 p0 = __halves2half2(hbuf[0], hbuf[1]); w.x = *(u32*)&p0;
        half2 p1 = __halves2half2(hbuf[2], hbuf[3]); w.y = *(u32*)&p1;
        half2 p2 = __halves2half2(hbuf[4], hbuf[5]); w.z = *(u32*)&p2;
        half2 p3 = __halves2half2(hbuf[6], hbuf[7]); w.w = *(u32*)&p3;
        *(uint4*)(g_vt + ((long)bh * 64 + d) * 1024 + lc * 128 + ls * 8) = w;
    }
}

// SMEM: sRed @0 (512B: [32 rows][4 wn] f32), red @512 (8 bufs x16 x 68 f32)
#define RED_OFF 512
#define RED_STRIDE 68
#define SMEM_BYTES (512 + 8 * 16 * RED_STRIDE * 4)

__global__ __launch_bounds__(256, 2)
void attn_kernel(float* __restrict__ outp, float* __restrict__ attnp) {
    extern __shared__ char smem[];
    float* sRed = (float*)smem;
    float* red = (float*)(smem + RED_OFF);

    const int t = threadIdx.x;
    const int tx = t & 31;
    const int ty = t >> 5;
    const int wm = ty & 1;            // m16 group
    const int wn = ty >> 1;           // 32-key slice per 128-tile
    const int bh = blockIdx.y;
    const int q0 = blockIdx.x * 32;
    const int g = tx >> 2;            // fragment group 0..7
    const int ltg = tx & 3;           // thread-in-group

    // permuted key offset within warp's 32-key window:
    // C col-slot (nt, 2c+e) holds key 8c + 2nt + e  ->  this thread (g as B n-slot)
    const int keyperm = 8 * (g >> 1) + (g & 1);

    const __half* Qt = g_qh + ((long)bh * L_ + q0 + 16 * wm + g) * D_ + 8 * ltg;
    const __half* Kt = g_kh + ((long)bh * L_ + wn * 32 + keyperm) * D_ + 8 * ltg;
    const __half* Vt = g_vt + ((long)bh * 64 + g) * 1024 + wn * 32 + 8 * ltg;

    u32 ph[64];          // S/exp fragments, PV-A-ready order
    u32 qa[2][2][4];     // Q A-frags: [g32][j][4], k-permuted

    // hoist Q fragments (4x LDG.128)
#pragma unroll
    for (int g32 = 0; g32 < 2; g32++) {
        uint4 lo = *(const uint4*)(Qt + 32 * g32);
        uint4 hi = *(const uint4*)(Qt + 8 * D_ + 32 * g32);
        qa[g32][0][0] = lo.x; qa[g32][0][1] = hi.x; qa[g32][0][2] = lo.y; qa[g32][0][3] = hi.y;
        qa[g32][1][0] = lo.z; qa[g32][1][1] = hi.z; qa[g32][1][2] = lo.w; qa[g32][1][3] = hi.w;
    }

    // ================= phase 1: S = Qn Kn^T (direct-LDG fragments) =================
#pragma unroll
    for (int kt = 0; kt < 8; kt++) {
        const __half* Kp = Kt + kt * 128 * D_;
        float c4[4][4];
#pragma unroll
        for (int nt = 0; nt < 4; nt++) {
            c4[nt][0] = 0.0f; c4[nt][1] = 0.0f; c4[nt][2] = 0.0f; c4[nt][3] = 0.0f;
        }
#pragma unroll
        for (int nt = 0; nt < 4; nt++) {
#pragma unroll
            for (int g32 = 0; g32 < 2; g32++) {
                const uint4 kk = *(const uint4*)(Kp + nt * 2 * D_ + 32 * g32);
                hmma(c4[nt], qa[g32][0], kk.x, kk.y);
                hmma(c4[nt], qa[g32][1], kk.z, kk.w);
            }
        }
#pragma unroll
        for (int nt = 0; nt < 4; nt++) {
            ph[kt * 8 + 2 * nt]     = pack_h2(c4[nt][0] * INV_TEMP, c4[nt][1] * INV_TEMP);
            ph[kt * 8 + 2 * nt + 1] = pack_h2(c4[nt][2] * INV_TEMP, c4[nt][3] * INV_TEMP);
        }
    }

    // ================= softmax sums (no max shift; |logit| <= 0.125) ===============
    float slo = 0.0f, shi = 0.0f;
#pragma unroll
    for (int i = 0; i < 64; i++) {
        float2 f = __half22float2(*(half2*)&ph[i]);
        float e0 = __expf(f.x);
        float e1 = __expf(f.y);
        if ((i & 1) == 0) slo += e0 + e1; else shi += e0 + e1;
        ph[i] = pack_h2(e0, e1);           // keep UNNORMALIZED exp
    }
    slo += __shfl_xor_sync(0xffffffffu, slo, 1);
    slo += __shfl_xor_sync(0xffffffffu, slo, 2);
    shi += __shfl_xor_sync(0xffffffffu, shi, 1);
    shi += __shfl_xor_sync(0xffffffffu, shi, 2);
    if (ltg == 0) {
        sRed[(16 * wm + g) * 4 + wn] = slo;
        sRed[(16 * wm + g + 8) * 4 + wn] = shi;
    }
    __syncthreads();
    float inv_lo, inv_hi;
    {
        const int rlo = (16 * wm + g) * 4;
        const int rhi = (16 * wm + g + 8) * 4;
        inv_lo = 1.0f / (sRed[rlo] + sRed[rlo + 1] + sRed[rlo + 2] + sRed[rlo + 3]);
        inv_hi = 1.0f / (sRed[rhi] + sRed[rhi + 1] + sRed[rhi + 2] + sRed[rhi + 3]);
    }

    // ---- write attn: thread owns 8 contiguous cols per (kt,row) -> 2x float4 ----
    {
        float* baseq = attnp + ((long)bh * L_ + q0 + 16 * wm + g) * L_ + wn * 32 + 8 * ltg;
#pragma unroll
        for (int kt = 0; kt < 8; kt++) {
#pragma unroll
            for (int r = 0; r < 2; r++) {
                const float inv = r ? inv_hi : inv_lo;
                float2 e0 = __half22float2(*(half2*)&ph[kt * 8 + 0 + r]);
                float2 e1 = __half22float2(*(half2*)&ph[kt * 8 + 2 + r]);
                float2 e2 = __half22float2(*(half2*)&ph[kt * 8 + 4 + r]);
                float2 e3 = __half22float2(*(half2*)&ph[kt * 8 + 6 + r]);
                float* p = baseq + (long)r * 8 * L_ + kt * 128;
                __stcs((float4*)p,       make_float4(e0.x * inv, e0.y * inv, e1.x * inv, e1.y * inv));
                __stcs((float4*)(p + 4), make_float4(e2.x * inv, e2.y * inv, e3.x * inv, e3.y * inv));
            }
        }
    }

    // ================= phase 3: O partials = exp(S) @ V (direct-LDG V^T) ==========
    float oc[8][4];
#pragma unroll
    for (int d = 0; d < 8; d++) {
        oc[d][0] = 0.0f; oc[d][1] = 0.0f; oc[d][2] = 0.0f; oc[d][3] = 0.0f;
    }

#pragma unroll
    for (int vc = 0; vc < 8; vc++) {
        const __half* Vp = Vt + vc * 128;
#pragma unroll
        for (int db = 0; db < 8; db++) {
            const uint4 vv = *(const uint4*)(Vp + (long)db * 8 * 1024);
            hmma(oc[db], &ph[vc * 8],     vv.x, vv.y);
            hmma(oc[db], &ph[vc * 8 + 4], vv.z, vv.w);
        }
    }

    // ================= O reduction across 4 wn (scaled by 1/Z) ====================
    {
        const int buf = (wm * 4 + wn) * 16;
#pragma unroll
        for (int db = 0; db < 8; db++) {
            const int ncol = 8 * db + 2 * ltg;
            *(float2*)&red[(buf + g) * RED_STRIDE + ncol] =
                make_float2(oc[db][0] * inv_lo, oc[db][1] * inv_lo);
            *(float2*)&red[(buf + g + 8) * RED_STRIDE + ncol] =
                make_float2(oc[db][2] * inv_hi, oc[db][3] * inv_hi);
        }
    }
    __syncthreads();
    {
        const int r = t >> 3;          // output row 0..31
        const int seg = t & 7;         // 8-float segment
        float acc[8];
#pragma unroll
        for (int j = 0; j < 8; j++) acc[j] = 0.0f;
#pragma unroll
        for (int w = 0; w < 4; w++) {
            const float* src = &red[(((r >> 4) * 4 + w) * 16 + (r & 15)) * RED_STRIDE + seg * 8];
#pragma unroll
            for (int j = 0; j < 8; j++) acc[j] += src[j];
        }
        float* dst = outp + ((long)bh * L_ + q0 + r) * D_ + seg * 8;
        *(float4*)dst       = make_float4(acc[0], acc[1], acc[2], acc[3]);
        *(float4*)(dst + 4) = make_float4(acc[4], acc[5], acc[6], acc[7]);
    }
}

extern "C" void kernel_launch(void* const* d_in, const int* in_sizes, int n_in,
                              void* d_out, int out_size) {
    const float* q = (const float*)d_in[0];
    const float* k = (const float*)d_in[1];
    const float* v = (const float*)d_in[2];
    float* outp  = (float*)d_out;
    float* attnp = outp + (long)BH_ * L_ * D_;

    prep_kernel<<<2048, 256>>>(q, k);
    dim3 vg(8, 32);
    vt_kernel<<<vg, 256>>>(v);

    cudaFuncSetAttribute(attn_kernel, cudaFuncAttributeMaxDynamicSharedMemorySize,
                         SMEM_BYTES);
    dim3 grid(L_ / 32, BH_);
    attn_kernel<<<grid, 256, SMEM_BYTES>>>(outp, attnp);
}

// round 11
// speedup vs baseline: 1.0836x; 1.0836x over previous
#include <cuda_runtime.h>
#include <cuda_fp16.h>
#include <stdint.h>
#include <math.h>

#define B_ 4
#define L_ 1024
#define H_ 8
#define D_ 64
#define BH_ 32
#define INV_TEMP 0.125f

typedef unsigned int u32;

// fragment-major packed operands, 128KB per head each
__device__ __align__(16) __half g_qf[BH_ * 65536];
__device__ __align__(16) __half g_kf[BH_ * 65536];
__device__ __align__(16) __half g_vf[BH_ * 65536];

__device__ __forceinline__ void hmma(float* c, const u32* a, u32 b0, u32 b1) {
    asm volatile(
        "mma.sync.aligned.m16n8k16.row.col.f32.f16.f16.f32 "
        "{%0,%1,%2,%3}, {%4,%5,%6,%7}, {%8,%9}, {%0,%1,%2,%3};"
        : "+f"(c[0]), "+f"(c[1]), "+f"(c[2]), "+f"(c[3])
        : "r"(a[0]), "r"(a[1]), "r"(a[2]), "r"(a[3]), "r"(b0), "r"(b1));
}
__device__ __forceinline__ u32 pack_h2(float a, float b) {
    half2 h = __floats2half2_rn(a, b);
    return *(u32*)&h;
}

// ---- prep: L2-normalize q,k; write FRAGMENT-MAJOR fp16 layouts ----
// Q' seg = wm*4 + g32*2 + lohi; element: row qt*32 + wm*16 + lohi*8 + g, d-chunk cc=ltg+4*g32
// K' window w=l>>5, seg = nt*2 + g32; key_local = 8*(g>>1)+(g&1)+2*nt, d-chunk cc=ltg+4*g32
__global__ void prep_kernel(const float* __restrict__ q,
                            const float* __restrict__ k) {
    const int gw = (blockIdx.x * blockDim.x + threadIdx.x) >> 5;
    const int lane = threadIdx.x & 31;
    const int r = gw * 2 + (lane >> 4);
    const int c4 = lane & 15;            // 4-float chunk of d
    const int b = r / (L_ * H_);
    const int rem = r % (L_ * H_);
    const int l = rem / H_;
    const int h = rem % H_;
    const int bh = b * H_ + h;
    const long src = (((long)b * L_ + l) * H_ + h) * D_ + c4 * 4;

    const int cc = c4 >> 1;              // 16B d-chunk 0..7
    const int ltg = cc & 3;
    const int g32 = cc >> 2;
    const int half8 = (c4 & 1) * 4;      // half-offset within 16B chunk

    // ---- q ----
    float4 qv = *(const float4*)(q + src);
    float ss = qv.x * qv.x + qv.y * qv.y + qv.z * qv.z + qv.w * qv.w;
#pragma unroll
    for (int o = 1; o < 16; o <<= 1) ss += __shfl_xor_sync(0xffffffffu, ss, o);
    float sc = 1.0f / fmaxf(sqrtf(ss), 1e-8f);
    uint2 pk;
    pk.x = pack_h2(qv.x * sc, qv.y * sc);
    pk.y = pack_h2(qv.z * sc, qv.w * sc);
    {
        const int qt = l >> 5;
        const int rl = l & 31;
        const int wm = rl >> 4;
        const int lohi = (rl >> 3) & 1;
        const int g = rl & 7;
        const long dst = (long)bh * 65536 + qt * 2048 +
                         (wm * 4 + g32 * 2 + lohi) * 256 + (4 * g + ltg) * 8 + half8;
        *(uint2*)(g_qf + dst) = pk;
    }

    // ---- k ----
    float4 kv = *(const float4*)(k + src);
    ss = kv.x * kv.x + kv.y * kv.y + kv.z * kv.z + kv.w * kv.w;
#pragma unroll
    for (int o = 1; o < 16; o <<= 1) ss += __shfl_xor_sync(0xffffffffu, ss, o);
    sc = 1.0f / fmaxf(sqrtf(ss), 1e-8f);
    pk.x = pack_h2(kv.x * sc, kv.y * sc);
    pk.y = pack_h2(kv.z * sc, kv.w * sc);
    {
        const int w = l >> 5;
        const int kl = l & 31;
        const int nt = (kl >> 1) & 3;
        const int g = 2 * (kl >> 3) + (kl & 1);
        const long dst = (long)bh * 65536 + w * 2048 +
                         (nt * 2 + g32) * 256 + (4 * g + ltg) * 8 + half8;
        *(uint2*)(g_kf + dst) = pk;
    }
}

// ---- vt: V [B,L,H,D] f32 -> fragment-major V' (transposed d-major fragments) ----
#define VT_S 73
__global__ void vt_kernel(const float* __restrict__ v) {
    __shared__ __half tile[128 * VT_S];
    const int t = threadIdx.x;
    const int lc = blockIdx.x;            // l-chunk of 128 (== vc)
    const int bh = blockIdx.y;
    const int b = bh >> 3;
    const int h = bh & 7;

#pragma unroll
    for (int i = 0; i < 32; i++) {
        const int idx = t + 256 * i;      // over 128*64
        const int row = idx >> 6;
        const int col = idx & 63;
        const long src = (((long)(b * 1024 + lc * 128 + row)) * 8 + h) * 64 + col;
        tile[row * VT_S + col] = __float2half(v[src]);
    }
    __syncthreads();

#pragma unroll
    for (int pass = 0; pass < 4; pass++) {
        const int d = (t >> 4) + 16 * pass;
        const int ls = t & 15;            // 8-key chunk within 128
        __half hbuf[8];
#pragma unroll
        for (int kk = 0; kk < 8; kk++) hbuf[kk] = tile[(ls * 8 + kk) * VT_S + d];
        uint4 w;
        half2 p0 = __halves2half2(hbuf[0], hbuf[1]); w.x = *(u32*)&p0;
        half2 p1 = __halves2half2(hbuf[2], hbuf[3]); w.y = *(u32*)&p1;
        half2 p2 = __halves2half2(hbuf[4], hbuf[5]); w.z = *(u32*)&p2;
        half2 p3 = __halves2half2(hbuf[6], hbuf[7]); w.w = *(u32*)&p3;
        // V' address: [bh][(vc*4+wn)*8+db][lane=4g+ltg]
        const int wn = ls >> 2;
        const int ltg = ls & 3;
        const int db = d >> 3;
        const int g = d & 7;
        const long dst = (long)bh * 65536 + ((lc * 4 + wn) * 8 + db) * 256 +
                         (4 * g + ltg) * 8;
        *(uint4*)(g_vf + dst) = w;
    }
}

// SMEM: sRed @0 (512B), red @512 (8 bufs x16 x 68 f32)
#define RED_OFF 512
#define RED_STRIDE 68
#define SMEM_BYTES (512 + 8 * 16 * RED_STRIDE * 4)

__global__ __launch_bounds__(256, 2)
void attn_kernel(float* __restrict__ outp, float* __restrict__ attnp) {
    extern __shared__ char smem[];
    float* sRed = (float*)smem;
    float* red = (float*)(smem + RED_OFF);

    const int t = threadIdx.x;
    const int tx = t & 31;
    const int ty = t >> 5;
    const int wm = ty & 1;            // m16 group
    const int wn = ty >> 1;           // 32-key slice per 128-tile
    const int bh = blockIdx.y;
    const int q0 = blockIdx.x * 32;
    const int g = tx >> 2;
    const int ltg = tx & 3;

    const __half* Qf = g_qf + (long)bh * 65536 + blockIdx.x * 2048;
    const __half* Kf = g_kf + (long)bh * 65536;
    const __half* Vf = g_vf + (long)bh * 65536;

    u32 ph[64];          // exp(S) fragments, PV-A-ready order
    u32 qa[2][2][4];     // Q A-frags

    // Q fragments: 4 coalesced LDG.128
#pragma unroll
    for (int g32 = 0; g32 < 2; g32++) {
        const uint4 lo = *(const uint4*)(Qf + (wm * 4 + g32 * 2 + 0) * 256 + tx * 8);
        const uint4 hi = *(const uint4*)(Qf + (wm * 4 + g32 * 2 + 1) * 256 + tx * 8);
        qa[g32][0][0] = lo.x; qa[g32][0][1] = hi.x; qa[g32][0][2] = lo.y; qa[g32][0][3] = hi.y;
        qa[g32][1][0] = lo.z; qa[g32][1][1] = hi.z; qa[g32][1][2] = lo.w; qa[g32][1][3] = hi.w;
    }

    // ================= phase 1: S = Qn Kn^T (coalesced direct-LDG) =================
#pragma unroll
    for (int kt = 0; kt < 8; kt++) {
        const __half* Kw = Kf + (kt * 4 + wn) * 2048;
        float c4[4][4];
#pragma unroll
        for (int nt = 0; nt < 4; nt++) {
            c4[nt][0] = 0.0f; c4[nt][1] = 0.0f; c4[nt][2] = 0.0f; c4[nt][3] = 0.0f;
        }
#pragma unroll
        for (int nt = 0; nt < 4; nt++) {
#pragma unroll
            for (int g32 = 0; g32 < 2; g32++) {
                const uint4 kk = *(const uint4*)(Kw + (nt * 2 + g32) * 256 + tx * 8);
                hmma(c4[nt], qa[g32][0], kk.x, kk.y);
                hmma(c4[nt], qa[g32][1], kk.z, kk.w);
            }
        }
#pragma unroll
        for (int nt = 0; nt < 4; nt++) {
            ph[kt * 8 + 2 * nt]     = pack_h2(c4[nt][0] * INV_TEMP, c4[nt][1] * INV_TEMP);
            ph[kt * 8 + 2 * nt + 1] = pack_h2(c4[nt][2] * INV_TEMP, c4[nt][3] * INV_TEMP);
        }
    }

    // ================= softmax sums (no max shift; |logit| <= 0.125) ===============
    float slo = 0.0f, shi = 0.0f;
#pragma unroll
    for (int i = 0; i < 64; i++) {
        float2 f = __half22float2(*(half2*)&ph[i]);
        float e0 = __expf(f.x);
        float e1 = __expf(f.y);
        if ((i & 1) == 0) slo += e0 + e1; else shi += e0 + e1;
        ph[i] = pack_h2(e0, e1);           // keep UNNORMALIZED exp
    }
    slo += __shfl_xor_sync(0xffffffffu, slo, 1);
    slo += __shfl_xor_sync(0xffffffffu, slo, 2);
    shi += __shfl_xor_sync(0xffffffffu, shi, 1);
    shi += __shfl_xor_sync(0xffffffffu, shi, 2);
    if (ltg == 0) {
        sRed[(16 * wm + g) * 4 + wn] = slo;
        sRed[(16 * wm + g + 8) * 4 + wn] = shi;
    }
    __syncthreads();
    float inv_lo, inv_hi;
    {
        const int rlo = (16 * wm + g) * 4;
        const int rhi = (16 * wm + g + 8) * 4;
        inv_lo = 1.0f / (sRed[rlo] + sRed[rlo + 1] + sRed[rlo + 2] + sRed[rlo + 3]);
        inv_hi = 1.0f / (sRed[rhi] + sRed[rhi + 1] + sRed[rhi + 2] + sRed[rhi + 3]);
    }

    // ---- write attn: thread owns 8 contiguous cols per (kt,row) -> 2x float4 ----
    {
        float* baseq = attnp + ((long)bh * L_ + q0 + 16 * wm + g) * L_ + wn * 32 + 8 * ltg;
#pragma unroll
        for (int kt = 0; kt < 8; kt++) {
#pragma unroll
            for (int r = 0; r < 2; r++) {
                const float inv = r ? inv_hi : inv_lo;
                float2 e0 = __half22float2(*(half2*)&ph[kt * 8 + 0 + r]);
                float2 e1 = __half22float2(*(half2*)&ph[kt * 8 + 2 + r]);
                float2 e2 = __half22float2(*(half2*)&ph[kt * 8 + 4 + r]);
                float2 e3 = __half22float2(*(half2*)&ph[kt * 8 + 6 + r]);
                float* p = baseq + (long)r * 8 * L_ + kt * 128;
                __stcs((float4*)p,       make_float4(e0.x * inv, e0.y * inv, e1.x * inv, e1.y * inv));
                __stcs((float4*)(p + 4), make_float4(e2.x * inv, e2.y * inv, e3.x * inv, e3.y * inv));
            }
        }
    }

    // ================= phase 3: O partials = exp(S) @ V' (coalesced LDG) ==========
    float oc[8][4];
#pragma unroll
    for (int d = 0; d < 8; d++) {
        oc[d][0] = 0.0f; oc[d][1] = 0.0f; oc[d][2] = 0.0f; oc[d][3] = 0.0f;
    }

#pragma unroll
    for (int vc = 0; vc < 8; vc++) {
        const __half* Vw = Vf + (vc * 4 + wn) * 2048;
#pragma unroll
        for (int db = 0; db < 8; db++) {
            const uint4 vv = *(const uint4*)(Vw + db * 256 + tx * 8);
            hmma(oc[db], &ph[vc * 8],     vv.x, vv.y);
            hmma(oc[db], &ph[vc * 8 + 4], vv.z, vv.w);
        }
    }

    // ================= O reduction across 4 wn (scaled by 1/Z) ====================
    {
        const int buf = (wm * 4 + wn) * 16;
#pragma unroll
        for (int db = 0; db < 8; db++) {
            const int ncol = 8 * db + 2 * ltg;
            *(float2*)&red[(buf + g) * RED_STRIDE + ncol] =
                make_float2(oc[db][0] * inv_lo, oc[db][1] * inv_lo);
            *(float2*)&red[(buf + g + 8) * RED_STRIDE + ncol] =
                make_float2(oc[db][2] * inv_hi, oc[db][3] * inv_hi);
        }
    }
    __syncthreads();
    {
        const int r = t >> 3;
        const int seg = t & 7;
        float acc[8];
#pragma unroll
        for (int j = 0; j < 8; j++) acc[j] = 0.0f;
#pragma unroll
        for (int w = 0; w < 4; w++) {
            const float* src = &red[(((r >> 4) * 4 + w) * 16 + (r & 15)) * RED_STRIDE + seg * 8];
#pragma unroll
            for (int j = 0; j < 8; j++) acc[j] += src[j];
        }
        float* dst = outp + ((long)bh * L_ + q0 + r) * D_ + seg * 8;
        *(float4*)dst       = make_float4(acc[0], acc[1], acc[2], acc[3]);
        *(float4*)(dst + 4) = make_float4(acc[4], acc[5], acc[6], acc[7]);
    }
}

extern "C" void kernel_launch(void* const* d_in, const int* in_sizes, int n_in,
                              void* d_out, int out_size) {
    const float* q = (const float*)d_in[0];
    const float* k = (const float*)d_in[1];
    const float* v = (const float*)d_in[2];
    float* outp  = (float*)d_out;
    float* attnp = outp + (long)BH_ * L_ * D_;

    prep_kernel<<<2048, 256>>>(q, k);
    dim3 vg(8, 32);
    vt_kernel<<<vg, 256>>>(v);

    cudaFuncSetAttribute(attn_kernel, cudaFuncAttributeMaxDynamicSharedMemorySize,
                         SMEM_BYTES);
    dim3 grid(L_ / 32, BH_);
    attn_kernel<<<grid, 256, SMEM_BYTES>>>(outp, attnp);
}

// round 12
// speedup vs baseline: 1.2752x; 1.1768x over previous
#include <cuda_runtime.h>
#include <cuda_fp16.h>
#include <stdint.h>
#include <math.h>

#define B_ 4
#define L_ 1024
#define H_ 8
#define D_ 64
#define BH_ 32
#define INV_TEMP 0.125f
#define KC 128

typedef unsigned int u32;

__device__ __align__(16) __half g_qh[BH_ * L_ * D_];
__device__ __align__(16) __half g_kh[BH_ * L_ * D_];
__device__ __align__(16) __half g_vf[BH_ * 65536];   // fragment-major V'

__device__ __forceinline__ void ldsm4(u32 addr, u32* r) {
    asm volatile("ldmatrix.sync.aligned.m8n8.x4.shared.b16 {%0,%1,%2,%3}, [%4];"
                 : "=r"(r[0]), "=r"(r[1]), "=r"(r[2]), "=r"(r[3]) : "r"(addr));
}
__device__ __forceinline__ void hmma(float* c, const u32* a, u32 b0, u32 b1) {
    asm volatile(
        "mma.sync.aligned.m16n8k16.row.col.f32.f16.f16.f32 "
        "{%0,%1,%2,%3}, {%4,%5,%6,%7}, {%8,%9}, {%0,%1,%2,%3};"
        : "+f"(c[0]), "+f"(c[1]), "+f"(c[2]), "+f"(c[3])
        : "r"(a[0]), "r"(a[1]), "r"(a[2]), "r"(a[3]), "r"(b0), "r"(b1));
}
__device__ __forceinline__ void cpa16(u32 dst, const void* src) {
    asm volatile("cp.async.cg.shared.global [%0], [%1], 16;" :: "r"(dst), "l"(src));
}
#define CPA_COMMIT() asm volatile("cp.async.commit_group;")
#define CPA_WAIT(n)  asm volatile("cp.async.wait_group " #n ";")

__device__ __forceinline__ u32 pack_h2(float a, float b) {
    half2 h = __floats2half2_rn(a, b);
    return *(u32*)&h;
}

// ---- prep: L2-normalize q,k -> fp16 [bh][l][d]; 2 rows per warp ----
__global__ void prep_kernel(const float* __restrict__ q,
                            const float* __restrict__ k) {
    const int gw = (blockIdx.x * blockDim.x + threadIdx.x) >> 5;
    const int lane = threadIdx.x & 31;
    const int r = gw * 2 + (lane >> 4);
    const int c4 = lane & 15;
    const int b = r / (L_ * H_);
    const int rem = r % (L_ * H_);
    const int l = rem / H_;
    const int h = rem % H_;
    const long src = (((long)b * L_ + l) * H_ + h) * D_ + c4 * 4;
    const long dst = (((long)b * H_ + h) * L_ + l) * D_ + c4 * 4;

    float4 qv = *(const float4*)(q + src);
    float ss = qv.x * qv.x + qv.y * qv.y + qv.z * qv.z + qv.w * qv.w;
#pragma unroll
    for (int o = 1; o < 16; o <<= 1) ss += __shfl_xor_sync(0xffffffffu, ss, o);
    float sc = 1.0f / fmaxf(sqrtf(ss), 1e-8f);
    uint2 pk;
    pk.x = pack_h2(qv.x * sc, qv.y * sc);
    pk.y = pack_h2(qv.z * sc, qv.w * sc);
    *(uint2*)(g_qh + dst) = pk;

    float4 kv = *(const float4*)(k + src);
    ss = kv.x * kv.x + kv.y * kv.y + kv.z * kv.z + kv.w * kv.w;
#pragma unroll
    for (int o = 1; o < 16; o <<= 1) ss += __shfl_xor_sync(0xffffffffu, ss, o);
    sc = 1.0f / fmaxf(sqrtf(ss), 1e-8f);
    pk.x = pack_h2(kv.x * sc, kv.y * sc);
    pk.y = pack_h2(kv.z * sc, kv.w * sc);
    *(uint2*)(g_kh + dst) = pk;
}

// ---- vt: V [B,L,H,D] f32 -> fragment-major V' f16 ----
// V'[bh][vc][wn][db][lane=4g+ltg] (uint4) = V^T[d=8db+g][keys vc*128+wn*32+8ltg..+7]
#define VT_S 73
__global__ void vt_kernel(const float* __restrict__ v) {
    __shared__ __half tile[128 * VT_S];
    const int t = threadIdx.x;
    const int lc = blockIdx.x;            // l-chunk of 128 (== vc)
    const int bh = blockIdx.y;
    const int b = bh >> 3;
    const int h = bh & 7;

#pragma unroll
    for (int i = 0; i < 32; i++) {
        const int idx = t + 256 * i;      // over 128*64
        const int row = idx >> 6;
        const int col = idx & 63;
        const long src = (((long)(b * 1024 + lc * 128 + row)) * 8 + h) * 64 + col;
        tile[row * VT_S + col] = __float2half(v[src]);
    }
    __syncthreads();

#pragma unroll
    for (int pass = 0; pass < 4; pass++) {
        const int d = (t >> 4) + 16 * pass;
        const int ls = t & 15;            // 8-key chunk within 128
        __half hbuf[8];
#pragma unroll
        for (int kk = 0; kk < 8; kk++) hbuf[kk] = tile[(ls * 8 + kk) * VT_S + d];
        uint4 w;
        half2 p0 = __halves2half2(hbuf[0], hbuf[1]); w.x = *(u32*)&p0;
        half2 p1 = __halves2half2(hbuf[2], hbuf[3]); w.y = *(u32*)&p1;
        half2 p2 = __halves2half2(hbuf[4], hbuf[5]); w.z = *(u32*)&p2;
        half2 p3 = __halves2half2(hbuf[6], hbuf[7]); w.w = *(u32*)&p3;
        const int wn = ls >> 2;
        const int ltg = ls & 3;
        const long dst = (long)bh * 65536 +
                         ((((long)lc * 4 + wn) * 8 + (d >> 3)) * 32 + 4 * (d & 7) + ltg) * 8;
        *(uint4*)(g_vf + dst) = w;
    }
}

// SMEM: sQ @0 (4096B swizzled), sRed @4096 (512B), K ring @4608 (3x16384)
//       red (O-reduce) aliases the ring @4608
#define SQ_OFF   0
#define SRED_OFF 4096
#define SKV_OFF  4608
#define RED_OFF  4608
#define RED_STRIDE 68
#define SMEM_BYTES (4608 + 3 * 16384)

// async-load one 128x64 f16 K tile, rows PERMUTED within each 32-key window:
// key bits (c c p h e) -> smem row (p h c c e)
__device__ __forceinline__ void tile_load_async_perm(u32 dstu, const __half* src, int t) {
#pragma unroll
    for (int i = 0; i < 4; i++) {
        const int idx = t + 256 * i;
        const int row = idx >> 3;
        const int ch = idx & 7;
        const int srow = (row & ~31) | ((row & 4) << 2) | ((row & 2) << 2) |
                         ((row >> 2) & 6) | (row & 1);
        cpa16(dstu + (((srow << 3) | (ch ^ (srow & 7))) << 4), src + idx * 8);
    }
}

__global__ __launch_bounds__(256, 2)
void attn_kernel(float* __restrict__ outp, float* __restrict__ attnp) {
    extern __shared__ char smem[];
    const u32 sbase = (u32)__cvta_generic_to_shared(smem);
    const u32 sQu = sbase + SQ_OFF;
    const u32 skv0 = sbase + SKV_OFF;
    float* sRed = (float*)(smem + SRED_OFF);
    float* red = (float*)(smem + RED_OFF);

    const int t = threadIdx.x;
    const int tx = t & 31;
    const int ty = t >> 5;
    const int wm = ty & 1;            // m16 group
    const int wn = ty >> 1;           // 32-key slice per 128-tile
    const int bh = blockIdx.y;
    const int q0 = blockIdx.x * 32;
    const int g = tx >> 2;
    const int ltg = tx & 3;
    const int lm = tx >> 3;
    const int lr = tx & 7;

    const __half* Qg = g_qh + ((long)bh * L_ + q0) * D_;
    const __half* Kg = g_kh + (long)bh * L_ * D_;
    const __half* Vf = g_vf + (long)bh * 65536;

    u32 ph[64];        // exp(S) fragments, PV-A-ready (permuted keys)
    u32 qf[4][4];      // Q A-frags
    u32 fb[4];
    uint4 vbuf[4];     // V prefetch ring

    // Q tile -> SMEM (swizzled)
    {
        const uint4* src = (const uint4*)Qg;
        uint4* dst = (uint4*)(smem + SQ_OFF);
        const int row = t >> 3;
        const int ch = t & 7;
        dst[(row << 3) | (ch ^ (row & 7))] = src[t];
    }

    // prefetch K0, K1 (permuted rows)
    tile_load_async_perm(skv0, Kg, t);
    CPA_COMMIT();
    tile_load_async_perm(skv0 + 16384, Kg + KC * D_, t);
    CPA_COMMIT();

    // ================= phase 1: S fragments in registers =================
#pragma unroll
    for (int kt = 0; kt < 8; kt++) {
        CPA_WAIT(1);
        __syncthreads();
        if (kt == 0) {
#pragma unroll
            for (int kk = 0; kk < 4; kk++) {
                const int arow = 16 * wm + (lm & 1) * 8 + lr;
                const int ach = 2 * kk + (lm >> 1);
                ldsm4(sQu + arow * 128 + ((ach ^ (arow & 7)) << 4), qf[kk]);
            }
        }
        if (kt < 6) {
            tile_load_async_perm(skv0 + ((kt + 2) % 3) * 16384,
                                 Kg + (size_t)(kt + 2) * KC * D_, t);
            CPA_COMMIT();
        }

        const u32 sKVu = skv0 + (kt % 3) * 16384;
        float c[4][4];
#pragma unroll
        for (int nt = 0; nt < 4; nt++) {
            c[nt][0] = 0.0f; c[nt][1] = 0.0f; c[nt][2] = 0.0f; c[nt][3] = 0.0f;
        }
#pragma unroll
        for (int kk = 0; kk < 4; kk++) {
#pragma unroll
            for (int p = 0; p < 2; p++) {
                const int brow = wn * 32 + p * 16 + (lm >> 1) * 8 + lr;
                const int bch = 2 * kk + (lm & 1);
                ldsm4(sKVu + brow * 128 + ((bch ^ (brow & 7)) << 4), fb);
                hmma(c[2 * p], qf[kk], fb[0], fb[1]);
                hmma(c[2 * p + 1], qf[kk], fb[2], fb[3]);
            }
        }
#pragma unroll
        for (int pair = 0; pair < 2; pair++) {
            ph[kt * 8 + pair * 4 + 0] = pack_h2(c[2 * pair][0] * INV_TEMP, c[2 * pair][1] * INV_TEMP);
            ph[kt * 8 + pair * 4 + 1] = pack_h2(c[2 * pair][2] * INV_TEMP, c[2 * pair][3] * INV_TEMP);
            ph[kt * 8 + pair * 4 + 2] = pack_h2(c[2 * pair + 1][0] * INV_TEMP, c[2 * pair + 1][1] * INV_TEMP);
            ph[kt * 8 + pair * 4 + 3] = pack_h2(c[2 * pair + 1][2] * INV_TEMP, c[2 * pair + 1][3] * INV_TEMP);
        }
    }

    // early V prefetch (vc=0, db=0..3) — overlaps softmax
#pragma unroll
    for (int j = 0; j < 4; j++) {
        vbuf[j] = *(const uint4*)(Vf + (((long)wn * 8 + j) * 32 + tx) * 8);
    }

    // ================= softmax sums (no max shift; |logit| <= 0.125) ===============
    float slo = 0.0f, shi = 0.0f;
#pragma unroll
    for (int i = 0; i < 64; i++) {
        float2 f = __half22float2(*(half2*)&ph[i]);
        float e0 = __expf(f.x);
        float e1 = __expf(f.y);
        if ((i & 1) == 0) slo += e0 + e1; else shi += e0 + e1;
        ph[i] = pack_h2(e0, e1);           // keep UNNORMALIZED exp
    }
    slo += __shfl_xor_sync(0xffffffffu, slo, 1);
    slo += __shfl_xor_sync(0xffffffffu, slo, 2);
    shi += __shfl_xor_sync(0xffffffffu, shi, 1);
    shi += __shfl_xor_sync(0xffffffffu, shi, 2);
    if (ltg == 0) {
        sRed[(16 * wm + g) * 4 + wn] = slo;
        sRed[(16 * wm + g + 8) * 4 + wn] = shi;
    }
    __syncthreads();
    float inv_lo, inv_hi;
    {
        const int rlo = (16 * wm + g) * 4;
        const int rhi = (16 * wm + g + 8) * 4;
        inv_lo = 1.0f / (sRed[rlo] + sRed[rlo + 1] + sRed[rlo + 2] + sRed[rlo + 3]);
        inv_hi = 1.0f / (sRed[rhi] + sRed[rhi + 1] + sRed[rhi + 2] + sRed[rhi + 3]);
    }

    // ---- attn write: 8 contiguous cols per (row, kt) -> 2x STG.128 ----
    {
        float* rowp = attnp + ((long)bh * L_ + q0 + 16 * wm + g) * L_ + wn * 32 + 8 * ltg;
#pragma unroll
        for (int kt = 0; kt < 8; kt++) {
#pragma unroll
            for (int r = 0; r < 2; r++) {
                const float inv = r ? inv_hi : inv_lo;
                float2 e0 = __half22float2(*(half2*)&ph[kt * 8 + 0 + r]);
                float2 e1 = __half22float2(*(half2*)&ph[kt * 8 + 2 + r]);
                float2 e2 = __half22float2(*(half2*)&ph[kt * 8 + 4 + r]);
                float2 e3 = __half22float2(*(half2*)&ph[kt * 8 + 6 + r]);
                float* p = rowp + (long)r * 8 * L_ + kt * 128;
                __stcs((float4*)p,       make_float4(e0.x * inv, e0.y * inv, e1.x * inv, e1.y * inv));
                __stcs((float4*)(p + 4), make_float4(e2.x * inv, e2.y * inv, e3.x * inv, e3.y * inv));
            }
        }
    }

    // ================= phase 3: O partials = exp(S) @ V' (LDG + prefetch) =========
    float oc[8][4];
#pragma unroll
    for (int d = 0; d < 8; d++) {
        oc[d][0] = 0.0f; oc[d][1] = 0.0f; oc[d][2] = 0.0f; oc[d][3] = 0.0f;
    }

#pragma unroll
    for (int j = 0; j < 64; j++) {
        const int vc = j >> 3;
        const int db = j & 7;
        const uint4 v = vbuf[j & 3];
        if (j + 4 < 64) {
            const int jn = j + 4;
            vbuf[j & 3] = *(const uint4*)(Vf +
                (((((long)(jn >> 3)) * 4 + wn) * 8 + (jn & 7)) * 32 + tx) * 8);
        }
        hmma(oc[db], &ph[vc * 8],     v.x, v.y);
        hmma(oc[db], &ph[vc * 8 + 4], v.z, v.w);
    }

    // ================= O reduction across 4 wn (scaled by 1/Z) ====================
    {
        const int buf = (wm * 4 + wn) * 16;
#pragma unroll
        for (int db = 0; db < 8; db++) {
            const int ncol = 8 * db + 2 * ltg;
            *(float2*)&red[(buf + g) * RED_STRIDE + ncol] =
                make_float2(oc[db][0] * inv_lo, oc[db][1] * inv_lo);
            *(float2*)&red[(buf + g + 8) * RED_STRIDE + ncol] =
                make_float2(oc[db][2] * inv_hi, oc[db][3] * inv_hi);
        }
    }
    __syncthreads();
    {
        const int r = t >> 3;
        const int seg = t & 7;
        float acc[8];
#pragma unroll
        for (int j = 0; j < 8; j++) acc[j] = 0.0f;
#pragma unroll
        for (int w = 0; w < 4; w++) {
            const float* src = &red[(((r >> 4) * 4 + w) * 16 + (r & 15)) * RED_STRIDE + seg * 8];
#pragma unroll
            for (int j = 0; j < 8; j++) acc[j] += src[j];
        }
        float* dst = outp + ((long)bh * L_ + q0 + r) * D_ + seg * 8;
        *(float4*)dst       = make_float4(acc[0], acc[1], acc[2], acc[3]);
        *(float4*)(dst + 4) = make_float4(acc[4], acc[5], acc[6], acc[7]);
    }
}

extern "C" void kernel_launch(void* const* d_in, const int* in_sizes, int n_in,
                              void* d_out, int out_size) {
    const float* q = (const float*)d_in[0];
    const float* k = (const float*)d_in[1];
    const float* v = (const float*)d_in[2];
    float* outp  = (float*)d_out;
    float* attnp = outp + (long)BH_ * L_ * D_;

    prep_kernel<<<2048, 256>>>(q, k);
    dim3 vg(8, 32);
    vt_kernel<<<vg, 256>>>(v);

    cudaFuncSetAttribute(attn_kernel, cudaFuncAttributeMaxDynamicSharedMemorySize,
                         SMEM_BYTES);
    dim3 grid(L_ / 32, BH_);
    attn_kernel<<<grid, 256, SMEM_BYTES>>>(outp, attnp);
}